// round 1
// baseline (speedup 1.0000x reference)
#include <cuda_runtime.h>
#include <math.h>

// Problem constants (DepthNet_20512763806141)
#define Bv 2
#define Vv 3
#define Cv 8
#define Hv 128
#define Wv 160
#define Dv 64

// Transposed feature scratch: [V,B,H,W,C] layout, channels contiguous.
__device__ float g_featT[Vv * Bv * Hv * Wv * Cv];

// ---------------------------------------------------------------------------
// Kernel 1: transpose features [V,B,C,H,W] -> [V,B,H,W,C]
// ---------------------------------------------------------------------------
__global__ void transpose_feat_kernel(const float* __restrict__ f) {
    int idx = blockIdx.x * blockDim.x + threadIdx.x;
    const int N = Vv * Bv * Cv * Hv * Wv;
    if (idx >= N) return;
    // input layout [V,B,C,H,W], idx walks it linearly (coalesced read)
    int w = idx % Wv; int t = idx / Wv;
    int h = t % Hv;   t /= Hv;
    int c = t % Cv;   t /= Cv;
    int b = t % Bv;   int v = t / Bv;
    g_featT[((((v * Bv + b) * Hv + h) * Wv + w) * Cv) + c] = f[idx];
}

// ---------------------------------------------------------------------------
// Kernel 2: one warp per output pixel; lanes own depths d=lane and d=lane+32.
// ---------------------------------------------------------------------------
__global__ void __launch_bounds__(256)
depthnet_kernel(const float* __restrict__ proj,      // [B,V,3,4]
                const float* __restrict__ depthv,    // [B,D,H,W]
                const float* __restrict__ rw,        // [C]
                float* __restrict__ out)             // [B,H,W]
{
    const int gwarp = (blockIdx.x * blockDim.x + threadIdx.x) >> 5;
    const int lane  = threadIdx.x & 31;
    if (gwarp >= Bv * Hv * Wv) return;

    const int b  = gwarp / (Hv * Wv);
    const int hw = gwarp % (Hv * Wv);
    const int h  = hw / Wv;
    const int w  = hw % Wv;
    const float xf = (float)w, yf = (float)h;

    // reg weights (8 floats, broadcast across warp via L1)
    float rwv[Cv];
#pragma unroll
    for (int c = 0; c < Cv; c++) rwv[c] = __ldg(&rw[c]);

    // reference view features at this pixel (channels contiguous)
    const float* refp = g_featT + ((size_t)(0 * Bv + b) * Hv * Wv + hw) * Cv;
    float4 rA = *(const float4*)refp;
    float4 rB = *(const float4*)(refp + 4);
    const float ref[Cv] = {rA.x, rA.y, rA.z, rA.w, rB.x, rB.y, rB.z, rB.w};

    // per-source-view projection: rp = R @ [x,y,1], Tv = T column
    float rp[2][3], Tv[2][3];
#pragma unroll
    for (int i = 0; i < 2; i++) {
        const float* P = proj + (size_t)(b * Vv + (i + 1)) * 12;
#pragma unroll
        for (int r = 0; r < 3; r++) {
            float R0 = __ldg(&P[r * 4 + 0]);
            float R1 = __ldg(&P[r * 4 + 1]);
            float R2 = __ldg(&P[r * 4 + 2]);
            Tv[i][r] = __ldg(&P[r * 4 + 3]);
            rp[i][r] = fmaf(R0, xf, fmaf(R1, yf, R2));
        }
    }

    float cost[2], depk[2];
    float mloc = -INFINITY;

#pragma unroll
    for (int k = 0; k < 2; k++) {
        const int d = lane + 32 * k;
        const float dep = depthv[(size_t)(b * Dv + d) * Hv * Wv + hw];
        depk[k] = dep;
        const float invd = 1.0f / dep;

        float sum[Cv], sq[Cv];
#pragma unroll
        for (int c = 0; c < Cv; c++) { sum[c] = ref[c]; sq[c] = ref[c] * ref[c]; }
        float inm = 1.0f;

#pragma unroll
        for (int i = 0; i < 2; i++) {
            const float sx = fmaf(Tv[i][0], invd, rp[i][0]);
            const float sy = fmaf(Tv[i][1], invd, rp[i][1]);
            const float sz = fmaf(Tv[i][2], invd, rp[i][2]);
            const float ix = sx / sz;  // align_corners denorm is identity
            const float iy = sy / sz;

            // in-view mask: strict interior (grid in (-1,1)); NaN compares false
            if (ix > 0.0f && ix < (float)(Wv - 1) && iy > 0.0f && iy < (float)(Hv - 1))
                inm += 1.0f;

            float wv[Cv];
            const bool near = (ix > -1.0f) && (ix < (float)Wv) &&
                              (iy > -1.0f) && (iy < (float)Hv);
            if (near) {
                const float x0f = floorf(ix), y0f = floorf(iy);
                const float fx = ix - x0f, fy = iy - y0f;
                const int x0 = (int)x0f, y0 = (int)y0f;
                const float gx1 = 1.0f - fx, gy1 = 1.0f - fy;
                float w00 = gx1 * gy1, w10 = fx * gy1, w01 = gx1 * fy, w11 = fx * fy;
                // per-corner validity (zeros padding)
                const float vx0 = (x0 >= 0) ? 1.0f : 0.0f;
                const float vx1 = (x0 + 1 <= Wv - 1) ? 1.0f : 0.0f;
                const float vy0 = (y0 >= 0) ? 1.0f : 0.0f;
                const float vy1 = (y0 + 1 <= Hv - 1) ? 1.0f : 0.0f;
                w00 *= vx0 * vy0; w10 *= vx1 * vy0;
                w01 *= vx0 * vy1; w11 *= vx1 * vy1;
                const int xc0 = max(x0, 0), xc1 = min(x0 + 1, Wv - 1);
                const int yc0 = max(y0, 0), yc1 = min(y0 + 1, Hv - 1);

                const float* base = g_featT + (size_t)((i + 1) * Bv + b) * Hv * Wv * Cv;
                const float4* p00 = (const float4*)(base + (size_t)(yc0 * Wv + xc0) * Cv);
                const float4* p10 = (const float4*)(base + (size_t)(yc0 * Wv + xc1) * Cv);
                const float4* p01 = (const float4*)(base + (size_t)(yc1 * Wv + xc0) * Cv);
                const float4* p11 = (const float4*)(base + (size_t)(yc1 * Wv + xc1) * Cv);
                float4 a00 = p00[0], b00 = p00[1];
                float4 a10 = p10[0], b10 = p10[1];
                float4 a01 = p01[0], b01 = p01[1];
                float4 a11 = p11[0], b11 = p11[1];
                const float* v00 = (const float*)&a00;  // a00,b00 contiguous on stack? no —
                // unpack explicitly instead:
                float c00[Cv] = {a00.x,a00.y,a00.z,a00.w,b00.x,b00.y,b00.z,b00.w};
                float c10[Cv] = {a10.x,a10.y,a10.z,a10.w,b10.x,b10.y,b10.z,b10.w};
                float c01[Cv] = {a01.x,a01.y,a01.z,a01.w,b01.x,b01.y,b01.z,b01.w};
                float c11[Cv] = {a11.x,a11.y,a11.z,a11.w,b11.x,b11.y,b11.z,b11.w};
                (void)v00;
#pragma unroll
                for (int c = 0; c < Cv; c++) {
                    float acc = c00[c] * w00;
                    acc = fmaf(c10[c], w10, acc);
                    acc = fmaf(c01[c], w01, acc);
                    acc = fmaf(c11[c], w11, acc);
                    wv[c] = acc;
                }
            } else {
                // fully outside: 0 if coords finite, NaN if not (matches wgt*valid NaN prop)
                const float nv = (isfinite(ix) && isfinite(iy))
                                     ? 0.0f
                                     : __int_as_float(0x7fffffff);
#pragma unroll
                for (int c = 0; c < Cv; c++) wv[c] = nv;
            }

#pragma unroll
            for (int c = 0; c < Cv; c++) {
                sum[c] += wv[c];
                sq[c]  = fmaf(wv[c], wv[c], sq[c]);
            }
        }

        const float cnt = 1.0f / inm;
        float cst = 0.0f;
#pragma unroll
        for (int c = 0; c < Cv; c++) {
            const float mean = sum[c] * cnt;
            const float feat = fmaf(-mean, mean, sq[c] * cnt);
            cst = fmaf(feat, rwv[c], cst);
        }
        cost[k] = cst;
        mloc = fmaxf(mloc, cst);
    }

    // warp softmax over D=64 (2 per lane)
#pragma unroll
    for (int o = 16; o; o >>= 1)
        mloc = fmaxf(mloc, __shfl_xor_sync(0xffffffffu, mloc, o));

    float num = 0.0f, den = 0.0f;
#pragma unroll
    for (int k = 0; k < 2; k++) {
        const float e = expf(cost[k] - mloc);
        num = fmaf(e, depk[k], num);
        den += e;
    }
#pragma unroll
    for (int o = 16; o; o >>= 1) {
        num += __shfl_xor_sync(0xffffffffu, num, o);
        den += __shfl_xor_sync(0xffffffffu, den, o);
    }

    if (lane == 0) out[gwarp] = num / den;
}

// ---------------------------------------------------------------------------
extern "C" void kernel_launch(void* const* d_in, const int* in_sizes, int n_in,
                              void* d_out, int out_size) {
    const float* features = (const float*)d_in[0];  // [V,B,C,H,W]
    const float* proj     = (const float*)d_in[1];  // [B,V,3,4]
    const float* depthv   = (const float*)d_in[2];  // [B,D,H,W]
    const float* rw       = (const float*)d_in[3];  // [C]
    float* out            = (float*)d_out;          // [B,H,W]
    (void)in_sizes; (void)n_in; (void)out_size;

    // 1) transpose features so channels are contiguous
    const int nT = Vv * Bv * Cv * Hv * Wv;
    transpose_feat_kernel<<<(nT + 255) / 256, 256>>>(features);

    // 2) main fused kernel: one warp per output pixel
    const int nwarps = Bv * Hv * Wv;           // 40960
    const int threads = nwarps * 32;           // 1,310,720
    depthnet_kernel<<<(threads + 255) / 256, 256>>>(proj, depthv, rw, out);
}

// round 2
// speedup vs baseline: 1.3628x; 1.3628x over previous
#include <cuda_runtime.h>
#include <cuda_fp16.h>
#include <math.h>

// Problem constants (DepthNet_20512763806141)
#define Bv 2
#define Vv 3
#define Cv 8
#define Hv 128
#define Wv 160
#define Dv 64
#define HWv (Hv * Wv)

// Scratch: features transposed+converted to fp16 [V,B,HW,C] (16B per pixel),
// depth values transposed to [B,HW,D] (lane-contiguous for the main kernel).
__device__ __half g_featH[Vv * Bv * HWv * Cv];
__device__ float  g_depT[Bv * HWv * Dv];

// ---------------------------------------------------------------------------
// Kernel 1: features [V,B,C,H,W] f32 -> [V,B,HW,C] fp16
// One thread per output pixel: 8 coalesced f32 reads, one 16B write.
// ---------------------------------------------------------------------------
__global__ void feat_prep_kernel(const float* __restrict__ f) {
    int idx = blockIdx.x * blockDim.x + threadIdx.x;  // over V*B*HW
    const int N = Vv * Bv * HWv;
    if (idx >= N) return;
    const int hw = idx % HWv;
    const int vb = idx / HWv;
    const float* src = f + ((size_t)vb * Cv) * HWv + hw;
    __half hbuf[Cv];
#pragma unroll
    for (int c = 0; c < Cv; c++) hbuf[c] = __float2half(src[(size_t)c * HWv]);
    *((uint4*)(g_featH) + idx) = *(const uint4*)hbuf;
}

// ---------------------------------------------------------------------------
// Kernel 2: depth [B,D,HW] -> [B,HW,D], 32x32 smem tile transpose.
// grid = (HW/32, D/32, B), block = (32,8)
// ---------------------------------------------------------------------------
__global__ void depth_transpose_kernel(const float* __restrict__ dv) {
    __shared__ float tile[32][33];
    const int b  = blockIdx.z;
    const int d0 = blockIdx.y * 32;
    const int p0 = blockIdx.x * 32;
    const int tx = threadIdx.x, ty = threadIdx.y;
#pragma unroll
    for (int j = 0; j < 32; j += 8)
        tile[ty + j][tx] = dv[((size_t)b * Dv + d0 + ty + j) * HWv + p0 + tx];
    __syncthreads();
#pragma unroll
    for (int j = 0; j < 32; j += 8)
        g_depT[((size_t)b * HWv + p0 + ty + j) * Dv + d0 + tx] = tile[tx][ty + j];
}

// ---------------------------------------------------------------------------
// Kernel 3: one warp per output pixel; lanes own depths d=lane and d=lane+32.
// ---------------------------------------------------------------------------
__device__ __forceinline__ void unpack8(uint4 v, float* o) {
    const __half2* hp = (const __half2*)&v;
#pragma unroll
    for (int j = 0; j < 4; j++) {
        float2 f = __half22float2(hp[j]);
        o[2 * j] = f.x; o[2 * j + 1] = f.y;
    }
}

__global__ void __launch_bounds__(256, 4)
depthnet_kernel(const float* __restrict__ proj,      // [B,V,3,4]
                const float* __restrict__ rw,        // [C]
                float* __restrict__ out)             // [B,HW]
{
    const int gwarp = (blockIdx.x * blockDim.x + threadIdx.x) >> 5;
    const int lane  = threadIdx.x & 31;
    if (gwarp >= Bv * HWv) return;

    const int b  = gwarp / HWv;
    const int hw = gwarp % HWv;
    const int h  = hw / Wv;
    const int w  = hw % Wv;
    const float xf = (float)w, yf = (float)h;

    // reg weights (broadcast)
    float rwv[Cv];
#pragma unroll
    for (int c = 0; c < Cv; c++) rwv[c] = __ldg(&rw[c]);

    // reference view features at this pixel (one 16B load, broadcast)
    float ref[Cv];
    unpack8(((const uint4*)g_featH)[(size_t)b * HWv + hw], ref);

    // per-source-view projection: rp = R @ [x,y,1], Tv = T column
    float rp[2][3], Tv[2][3];
#pragma unroll
    for (int i = 0; i < 2; i++) {
        const float* P = proj + (size_t)(b * Vv + (i + 1)) * 12;
#pragma unroll
        for (int r = 0; r < 3; r++) {
            float R0 = __ldg(&P[r * 4 + 0]);
            float R1 = __ldg(&P[r * 4 + 1]);
            float R2 = __ldg(&P[r * 4 + 2]);
            Tv[i][r] = __ldg(&P[r * 4 + 3]);
            rp[i][r] = fmaf(R0, xf, fmaf(R1, yf, R2));
        }
    }

    float cost[2], depk[2];
    float mloc = -INFINITY;

#pragma unroll
    for (int k = 0; k < 2; k++) {
        // lane-contiguous depth load from transposed layout
        const float dep = g_depT[((size_t)b * HWv + hw) * Dv + lane + 32 * k];
        depk[k] = dep;
        const float invd = __fdividef(1.0f, dep);

        float sum[Cv], sq[Cv];
#pragma unroll
        for (int c = 0; c < Cv; c++) { sum[c] = ref[c]; sq[c] = ref[c] * ref[c]; }
        float inm = 1.0f;

#pragma unroll
        for (int i = 0; i < 2; i++) {
            const float sx = fmaf(Tv[i][0], invd, rp[i][0]);
            const float sy = fmaf(Tv[i][1], invd, rp[i][1]);
            const float sz = fmaf(Tv[i][2], invd, rp[i][2]);
            const float ix = __fdividef(sx, sz);  // align_corners denorm is identity
            const float iy = __fdividef(sy, sz);

            // in-view mask: strict interior (grid in (-1,1)); NaN compares false
            if (ix > 0.0f && ix < (float)(Wv - 1) && iy > 0.0f && iy < (float)(Hv - 1))
                inm += 1.0f;

            float wv[Cv];
            const bool near = (ix > -1.0f) && (ix < (float)Wv) &&
                              (iy > -1.0f) && (iy < (float)Hv);
            if (near) {
                const float x0f = floorf(ix), y0f = floorf(iy);
                const float fx = ix - x0f, fy = iy - y0f;
                const int x0 = (int)x0f, y0 = (int)y0f;
                const float gx1 = 1.0f - fx, gy1 = 1.0f - fy;
                float w00 = gx1 * gy1, w10 = fx * gy1, w01 = gx1 * fy, w11 = fx * fy;
                // per-corner validity (zeros padding)
                if (x0 < 0)           { w00 = 0.0f; w01 = 0.0f; }
                if (x0 + 1 > Wv - 1)  { w10 = 0.0f; w11 = 0.0f; }
                if (y0 < 0)           { w00 = 0.0f; w10 = 0.0f; }
                if (y0 + 1 > Hv - 1)  { w01 = 0.0f; w11 = 0.0f; }
                const int xc0 = max(x0, 0), xc1 = min(x0 + 1, Wv - 1);
                const int yc0 = max(y0, 0), yc1 = min(y0 + 1, Hv - 1);

                const uint4* base = (const uint4*)g_featH +
                                    (size_t)((i + 1) * Bv + b) * HWv;
                // corner-sequential accumulation (limits live registers)
                float cbuf[Cv];
                unpack8(base[yc0 * Wv + xc0], cbuf);
#pragma unroll
                for (int c = 0; c < Cv; c++) wv[c] = cbuf[c] * w00;
                unpack8(base[yc0 * Wv + xc1], cbuf);
#pragma unroll
                for (int c = 0; c < Cv; c++) wv[c] = fmaf(cbuf[c], w10, wv[c]);
                unpack8(base[yc1 * Wv + xc0], cbuf);
#pragma unroll
                for (int c = 0; c < Cv; c++) wv[c] = fmaf(cbuf[c], w01, wv[c]);
                unpack8(base[yc1 * Wv + xc1], cbuf);
#pragma unroll
                for (int c = 0; c < Cv; c++) wv[c] = fmaf(cbuf[c], w11, wv[c]);
            } else {
                // fully outside: 0 if coords finite, NaN if not (matches wgt*valid NaN prop)
                const float nv = (isfinite(ix) && isfinite(iy))
                                     ? 0.0f
                                     : __int_as_float(0x7fffffff);
#pragma unroll
                for (int c = 0; c < Cv; c++) wv[c] = nv;
            }

#pragma unroll
            for (int c = 0; c < Cv; c++) {
                sum[c] += wv[c];
                sq[c]  = fmaf(wv[c], wv[c], sq[c]);
            }
        }

        const float cnt = __fdividef(1.0f, inm);
        float cst = 0.0f;
#pragma unroll
        for (int c = 0; c < Cv; c++) {
            const float mean = sum[c] * cnt;
            const float feat = fmaf(-mean, mean, sq[c] * cnt);
            cst = fmaf(feat, rwv[c], cst);
        }
        cost[k] = cst;
        mloc = fmaxf(mloc, cst);
    }

    // warp softmax over D=64 (2 per lane)
#pragma unroll
    for (int o = 16; o; o >>= 1)
        mloc = fmaxf(mloc, __shfl_xor_sync(0xffffffffu, mloc, o));

    float num = 0.0f, den = 0.0f;
#pragma unroll
    for (int k = 0; k < 2; k++) {
        const float e = __expf(cost[k] - mloc);
        num = fmaf(e, depk[k], num);
        den += e;
    }
#pragma unroll
    for (int o = 16; o; o >>= 1) {
        num += __shfl_xor_sync(0xffffffffu, num, o);
        den += __shfl_xor_sync(0xffffffffu, den, o);
    }

    if (lane == 0) out[gwarp] = __fdividef(num, den);
}

// ---------------------------------------------------------------------------
extern "C" void kernel_launch(void* const* d_in, const int* in_sizes, int n_in,
                              void* d_out, int out_size) {
    const float* features = (const float*)d_in[0];  // [V,B,C,H,W]
    const float* proj     = (const float*)d_in[1];  // [B,V,3,4]
    const float* depthv   = (const float*)d_in[2];  // [B,D,H,W]
    const float* rw       = (const float*)d_in[3];  // [C]
    float* out            = (float*)d_out;          // [B,HW]
    (void)in_sizes; (void)n_in; (void)out_size;

    // 1) features -> fp16 [V,B,HW,C]
    const int nF = Vv * Bv * HWv;
    feat_prep_kernel<<<(nF + 255) / 256, 256>>>(features);

    // 2) depth values -> [B,HW,D]
    dim3 tg(HWv / 32, Dv / 32, Bv);
    depth_transpose_kernel<<<tg, dim3(32, 8)>>>(depthv);

    // 3) main fused kernel: one warp per output pixel
    const int nwarps = Bv * HWv;               // 40960
    const int threads = nwarps * 32;
    depthnet_kernel<<<(threads + 255) / 256, 256>>>(proj, rw, out);
}